// round 14
// baseline (speedup 1.0000x reference)
#include <cuda_runtime.h>
#include <cuda_bf16.h>
#include <stdint.h>

#define NUM_USERS 100000
#define NUM_ITEMS 50000
#define N_NODES   (NUM_USERS + NUM_ITEMS)   // 150000
#define EMBED_DIM 64
#define N_EDGES   1000000

#define SCAN_BS   1024
#define N_SCAN_BLOCKS ((N_NODES + SCAN_BS - 1) / SCAN_BS)   // 147

#define A_FLAG (1u << 30)
#define P_FLAG (1u << 31)
#define VAL_MASK 0x3FFFFFFFu

// ---- static device scratch (no allocation allowed) ----
__device__ int      g_deg[N_NODES];
__device__ float    g_dinv[N_NODES];
__device__ int      g_off[N_NODES];        // excl prefix -> end offsets after scatter
__device__ unsigned g_part[N_SCAN_BLOCKS]; // lookback state (reset each call)
__device__ int2     g_csr[N_EDGES];        // {src, norm_bits}
__device__ float    g_x1[N_NODES * EMBED_DIM];
__device__ float    g_x2[N_NODES * EMBED_DIM];

// -------------------- setup kernels --------------------

__global__ void k_degree(const int* __restrict__ edge_index) {
    int e = blockIdx.x * blockDim.x + threadIdx.x;
    if (e < N_EDGES) atomicAdd(&g_deg[edge_index[N_EDGES + e]], 1);
}

// single-pass decoupled-lookback exclusive scan of degrees; also emits dinv.
__global__ void __launch_bounds__(SCAN_BS) k_scan() {
    __shared__ int s_wt[32];
    __shared__ int s_run;

    int tid  = threadIdx.x;
    int bid  = blockIdx.x;
    int lane = tid & 31;
    int wid  = tid >> 5;
    int i    = bid * SCAN_BS + tid;

    int v = (i < N_NODES) ? g_deg[i] : 0;
    if (i < N_NODES) g_dinv[i] = (v > 0) ? rsqrtf((float)v) : 0.0f;

    int inc = v;
    #pragma unroll
    for (int d = 1; d < 32; d <<= 1) {
        int t = __shfl_up_sync(0xffffffffu, inc, d);
        if (lane >= d) inc += t;
    }
    if (lane == 31) s_wt[wid] = inc;
    __syncthreads();

    if (wid == 0) {
        int wv = s_wt[lane];
        int winc = wv;
        #pragma unroll
        for (int d = 1; d < 32; d <<= 1) {
            int t = __shfl_up_sync(0xffffffffu, winc, d);
            if (lane >= d) winc += t;
        }
        s_wt[lane] = winc;
        if (lane == 31)
            atomicExch(&g_part[bid], A_FLAG | (unsigned)winc);

        int running = 0;
        int look = bid - 1;
        while (look >= 0) {
            int idx = look - lane;
            unsigned w;
            if (idx >= 0) {
                volatile unsigned* p = (volatile unsigned*)&g_part[idx];
                do { w = *p; } while ((w & (A_FLAG | P_FLAG)) == 0);
            } else {
                w = P_FLAG;
            }
            unsigned pm = __ballot_sync(0xffffffffu, (w & P_FLAG) != 0);
            int firstP = pm ? (__ffs(pm) - 1) : 32;
            int contrib = (lane <= firstP) ? (int)(w & VAL_MASK) : 0;
            #pragma unroll
            for (int d = 16; d; d >>= 1) contrib += __shfl_down_sync(0xffffffffu, contrib, d);
            contrib = __shfl_sync(0xffffffffu, contrib, 0);
            running += contrib;
            if (firstP < 32) break;
            look -= 32;
        }
        if (lane == 31)
            atomicExch(&g_part[bid], P_FLAG | (unsigned)(running + winc));
        if (lane == 0) s_run = running;
    }
    __syncthreads();

    int excl = (wid ? s_wt[wid - 1] : 0) + (inc - v) + s_run;
    if (i < N_NODES) g_off[i] = excl;
}

// scatter edges into CSR-by-dst; single atomic bumps g_off[dst] itself.
__global__ void k_scatter(const int* __restrict__ edge_index) {
    int e = blockIdx.x * blockDim.x + threadIdx.x;
    if (e < N_EDGES) {
        int src = edge_index[e];
        int dst = edge_index[N_EDGES + e];
        int pos = atomicAdd(&g_off[dst], 1);
        float norm = g_dinv[src] * g_dinv[dst];
        g_csr[pos] = make_int2(src, __float_as_int(norm));
    }
}

// -------------------- propagation --------------------
// 2 nodes per warp: 16 lanes per node, float4 per lane (16 x 16B = 256B row).
// Software-pipelined batches of 4 clamped edges: while the current batch's
// gathers + FMAs are in flight, the NEXT batch's csr entries are prefetched.
// launch_bounds(256,4) gives ptxas <=64 regs so the in-flight set stays live.
__device__ __forceinline__ float4 gather_node4(const float4* __restrict__ xin,
                                               int beg, int end, int qlane) {
    float4 sum = make_float4(0.0f, 0.0f, 0.0f, 0.0f);
    if (beg >= end) return sum;
    int last = end - 1;

    int e = beg;
    int2 p0 = g_csr[e];
    int2 p1 = g_csr[min(e + 1, last)];
    int2 p2 = g_csr[min(e + 2, last)];
    int2 p3 = g_csr[min(e + 3, last)];

    for (;;) {
        int en = e + 4;
        // prefetch next batch (clamped -> always in-bounds; unused on last trip)
        int2 q0 = g_csr[min(en,     last)];
        int2 q1 = g_csr[min(en + 1, last)];
        int2 q2 = g_csr[min(en + 2, last)];
        int2 q3 = g_csr[min(en + 3, last)];

        float4 v0 = xin[(size_t)p0.x * 16 + qlane];
        float4 v1 = xin[(size_t)p1.x * 16 + qlane];
        float4 v2 = xin[(size_t)p2.x * 16 + qlane];
        float4 v3 = xin[(size_t)p3.x * 16 + qlane];
        float w0 = __int_as_float(p0.y);
        float w1 = (e + 1 < end) ? __int_as_float(p1.y) : 0.0f;
        float w2 = (e + 2 < end) ? __int_as_float(p2.y) : 0.0f;
        float w3 = (e + 3 < end) ? __int_as_float(p3.y) : 0.0f;

        sum.x = fmaf(v0.x, w0, sum.x);  sum.y = fmaf(v0.y, w0, sum.y);
        sum.z = fmaf(v0.z, w0, sum.z);  sum.w = fmaf(v0.w, w0, sum.w);
        sum.x = fmaf(v1.x, w1, sum.x);  sum.y = fmaf(v1.y, w1, sum.y);
        sum.z = fmaf(v1.z, w1, sum.z);  sum.w = fmaf(v1.w, w1, sum.w);
        sum.x = fmaf(v2.x, w2, sum.x);  sum.y = fmaf(v2.y, w2, sum.y);
        sum.z = fmaf(v2.z, w2, sum.z);  sum.w = fmaf(v2.w, w2, sum.w);
        sum.x = fmaf(v3.x, w3, sum.x);  sum.y = fmaf(v3.y, w3, sum.y);
        sum.z = fmaf(v3.z, w3, sum.z);  sum.w = fmaf(v3.w, w3, sum.w);

        if (en >= end) break;
        e = en;
        p0 = q0; p1 = q1; p2 = q2; p3 = q3;
    }
    return sum;
}

// shifted-offset convention: end = g_off[node], beg = node ? g_off[node-1] : 0
__global__ void __launch_bounds__(256, 4) k_prop1(const float4* __restrict__ emb) {
    int gtid = blockIdx.x * blockDim.x + threadIdx.x;
    int node = gtid >> 4, qlane = gtid & 15;
    if (node >= N_NODES) return;
    int end = g_off[node];
    int beg = node ? g_off[node - 1] : 0;
    float4 sum = gather_node4(emb, beg, end, qlane);
    ((float4*)g_x1)[(size_t)node * 16 + qlane] = sum;
}

__global__ void __launch_bounds__(256, 4) k_prop2() {
    int gtid = blockIdx.x * blockDim.x + threadIdx.x;
    int node = gtid >> 4, qlane = gtid & 15;
    if (node >= N_NODES) return;
    int end = g_off[node];
    int beg = node ? g_off[node - 1] : 0;
    float4 sum = gather_node4((const float4*)g_x1, beg, end, qlane);
    ((float4*)g_x2)[(size_t)node * 16 + qlane] = sum;
}

// layer 3 + epilogue: out = 0.25*(emb + l1 + l2 + A~*l2)
__global__ void __launch_bounds__(256, 4) k_prop_last(const float4* __restrict__ emb,
                                                      float4* __restrict__ out) {
    int gtid = blockIdx.x * blockDim.x + threadIdx.x;
    int node = gtid >> 4, qlane = gtid & 15;
    if (node >= N_NODES) return;
    int end = g_off[node];
    int beg = node ? g_off[node - 1] : 0;
    float4 sum = gather_node4((const float4*)g_x2, beg, end, qlane);

    size_t oi = (size_t)node * 16 + qlane;
    float4 e0 = emb[oi];
    float4 a1 = ((const float4*)g_x1)[oi];
    float4 a2 = ((const float4*)g_x2)[oi];
    float4 o;
    o.x = 0.25f * (e0.x + a1.x + a2.x + sum.x);
    o.y = 0.25f * (e0.y + a1.y + a2.y + sum.y);
    o.z = 0.25f * (e0.z + a1.z + a2.z + sum.z);
    o.w = 0.25f * (e0.w + a1.w + a2.w + sum.w);
    out[oi] = o;
}

// -------------------- launch --------------------

extern "C" void kernel_launch(void* const* d_in, const int* in_sizes, int n_in,
                              void* d_out, int out_size) {
    const int*   edge_index = (const int*)d_in[0];     // int32
    const float* emb_weight = (const float*)d_in[1];
    float*       out        = (float*)d_out;

    void* deg_ptr = nullptr;  cudaGetSymbolAddress(&deg_ptr, g_deg);
    void* part_ptr = nullptr; cudaGetSymbolAddress(&part_ptr, g_part);
    cudaMemsetAsync(deg_ptr, 0, N_NODES * sizeof(int), 0);
    cudaMemsetAsync(part_ptr, 0, N_SCAN_BLOCKS * sizeof(unsigned), 0);

    const int BS = 256;
    int ge = (N_EDGES + BS - 1) / BS;

    k_degree<<<ge, BS>>>(edge_index);                // kernel 1
    k_scan<<<N_SCAN_BLOCKS, SCAN_BS>>>();            // kernel 2
    k_scatter<<<ge, BS>>>(edge_index);               // kernel 3

    int gp = (N_NODES * 16 + BS - 1) / BS;           // 16 threads per node
    k_prop1<<<gp, BS>>>((const float4*)emb_weight);            // kernel 4 <- ncu
    k_prop2<<<gp, BS>>>();                                     // kernel 5
    k_prop_last<<<gp, BS>>>((const float4*)emb_weight, (float4*)out); // kernel 6
}

// round 15
// speedup vs baseline: 1.2011x; 1.2011x over previous
#include <cuda_runtime.h>
#include <cuda_bf16.h>
#include <stdint.h>

#define NUM_USERS 100000
#define NUM_ITEMS 50000
#define N_NODES   (NUM_USERS + NUM_ITEMS)   // 150000
#define EMBED_DIM 64
#define N_EDGES   1000000

#define CSR_MAX   (N_EDGES + 3 * N_NODES)   // padded-to-4 upper bound (1.45M ints)

#define SCAN_BS   1024
#define N_SCAN_BLOCKS ((N_NODES + SCAN_BS - 1) / SCAN_BS)   // 147

#define A_FLAG (1u << 30)
#define P_FLAG (1u << 31)
#define VAL_MASK 0x3FFFFFFFu

// ---- static device scratch (no allocation allowed) ----
__device__ int      g_deg[N_NODES];
__device__ float    g_dinv[N_NODES];          // rsqrt(deg)
__device__ float    g_sdeg[N_NODES];          // sqrt(deg)
__device__ int      g_off[N_NODES + 1];       // exclusive prefix of PADDED degrees
__device__ int      g_cur[N_NODES];           // scatter cursors (zeroed in k_scan)
__device__ unsigned g_part[N_SCAN_BLOCKS];    // lookback state (zeroed in k_degree... see memset)
__device__ int      g_csr[CSR_MAX];           // src+1 per edge; pads = 0 -> zero row
// y arrays: row u+1 holds node u; row 0 is STATICALLY ZERO and never written.
__device__ float    g_y0[(N_NODES + 1) * EMBED_DIM];
__device__ float    g_y1[(N_NODES + 1) * EMBED_DIM];
__device__ float    g_y2[(N_NODES + 1) * EMBED_DIM];

// -------------------- setup kernels --------------------

// 2 edges per thread, vectorized; also zeroes the lookback state for k_scan.
__global__ void k_degree(const int* __restrict__ edge_index) {
    int t = blockIdx.x * blockDim.x + threadIdx.x;
    if (t < N_SCAN_BLOCKS) g_part[t] = 0;
    if (t < N_EDGES / 2) {
        int2 d2 = ((const int2*)(edge_index + N_EDGES))[t];
        atomicAdd(&g_deg[d2.x], 1);
        atomicAdd(&g_deg[d2.y], 1);
    }
}

// decoupled-lookback exclusive scan of PADDED degrees; emits dinv/sdeg,
// zeroes scatter cursors, and materializes y0 = emb * dinv (block-local range).
__global__ void __launch_bounds__(SCAN_BS) k_scan(const float4* __restrict__ emb) {
    __shared__ int s_wt[32];
    __shared__ int s_run;

    int tid  = threadIdx.x;
    int bid  = blockIdx.x;
    int lane = tid & 31;
    int wid  = tid >> 5;
    int i    = bid * SCAN_BS + tid;

    int d = (i < N_NODES) ? g_deg[i] : 0;
    if (i < N_NODES) {
        g_dinv[i] = (d > 0) ? rsqrtf((float)d) : 0.0f;
        g_sdeg[i] = sqrtf((float)d);
        g_cur[i]  = 0;
    }
    int v = (d + 3) & ~3;                        // padded degree

    int inc = v;
    #pragma unroll
    for (int s = 1; s < 32; s <<= 1) {
        int t = __shfl_up_sync(0xffffffffu, inc, s);
        if (lane >= s) inc += t;
    }
    if (lane == 31) s_wt[wid] = inc;
    __syncthreads();

    if (wid == 0) {
        int wv = s_wt[lane];
        int winc = wv;
        #pragma unroll
        for (int s = 1; s < 32; s <<= 1) {
            int t = __shfl_up_sync(0xffffffffu, winc, s);
            if (lane >= s) winc += t;
        }
        s_wt[lane] = winc;
        if (lane == 31)
            atomicExch(&g_part[bid], A_FLAG | (unsigned)winc);

        int running = 0;
        int look = bid - 1;
        while (look >= 0) {
            int idx = look - lane;
            unsigned w;
            if (idx >= 0) {
                volatile unsigned* p = (volatile unsigned*)&g_part[idx];
                do { w = *p; } while ((w & (A_FLAG | P_FLAG)) == 0);
            } else {
                w = P_FLAG;
            }
            unsigned pm = __ballot_sync(0xffffffffu, (w & P_FLAG) != 0);
            int firstP = pm ? (__ffs(pm) - 1) : 32;
            int contrib = (lane <= firstP) ? (int)(w & VAL_MASK) : 0;
            #pragma unroll
            for (int s = 16; s; s >>= 1) contrib += __shfl_down_sync(0xffffffffu, contrib, s);
            contrib = __shfl_sync(0xffffffffu, contrib, 0);
            running += contrib;
            if (firstP < 32) break;
            look -= 32;
        }
        if (lane == 31)
            atomicExch(&g_part[bid], P_FLAG | (unsigned)(running + winc));
        if (lane == 0) s_run = running;
    }
    __syncthreads();

    int excl = (wid ? s_wt[wid - 1] : 0) + (inc - v) + s_run;
    if (i < N_NODES) g_off[i] = excl;
    if (i == N_NODES - 1) g_off[N_NODES] = excl + v;

    // y0 = emb * dinv for this block's node range (dinv written above; synced)
    __syncthreads();
    int base = bid * SCAN_BS;
    float4* y0 = (float4*)g_y0;
    for (int j = tid; j < SCAN_BS * 16; j += SCAN_BS) {
        int node = base + (j >> 4);
        if (node < N_NODES) {
            float di = g_dinv[node];
            float4 e = emb[(size_t)node * 16 + (j & 15)];
            float4 o;
            o.x = e.x * di; o.y = e.y * di; o.z = e.z * di; o.w = e.w * di;
            y0[(size_t)(node + 1) * 16 + (j & 15)] = o;
        }
    }
}

// scatter 2 edges per thread; stores src+1 (4B). Pads stay 0 from memset.
__global__ void k_scatter(const int* __restrict__ edge_index) {
    int t = blockIdx.x * blockDim.x + threadIdx.x;
    if (t < N_EDGES / 2) {
        int2 s2 = ((const int2*)edge_index)[t];
        int2 d2 = ((const int2*)(edge_index + N_EDGES))[t];
        int p0 = g_off[d2.x] + atomicAdd(&g_cur[d2.x], 1);
        g_csr[p0] = s2.x + 1;
        int p1 = g_off[d2.y] + atomicAdd(&g_cur[d2.y], 1);
        g_csr[p1] = s2.y + 1;
    }
}

// -------------------- propagation --------------------
// 2 nodes per warp: 16 lanes per node, float4 per lane (16 x 16B = 256B row).
// Weight-free gather: per trip = 1x int4 csr load (4 srcs) + 4 gather LDG.128.
// Pad srcs are 0 -> zero row (L1-hot). No clamping, no weights.
__device__ __forceinline__ float4 gather_sum(const float4* __restrict__ yin,
                                             int beg, int nt, int qlane) {
    float4 sum = make_float4(0.0f, 0.0f, 0.0f, 0.0f);
    const int4* cp = (const int4*)(g_csr + beg);   // beg is a multiple of 4
    for (int t = 0; t < nt; t++) {
        int4 s = cp[t];
        float4 v0 = yin[(size_t)s.x * 16 + qlane];
        float4 v1 = yin[(size_t)s.y * 16 + qlane];
        float4 v2 = yin[(size_t)s.z * 16 + qlane];
        float4 v3 = yin[(size_t)s.w * 16 + qlane];
        float4 a, b;
        a.x = v0.x + v1.x;  a.y = v0.y + v1.y;  a.z = v0.z + v1.z;  a.w = v0.w + v1.w;
        b.x = v2.x + v3.x;  b.y = v2.y + v3.y;  b.z = v2.z + v3.z;  b.w = v2.w + v3.w;
        sum.x += a.x + b.x; sum.y += a.y + b.y; sum.z += a.z + b.z; sum.w += a.w + b.w;
    }
    return sum;
}

// y1 = dinv^2 * (A y0)
__global__ void __launch_bounds__(256) k_prop1() {
    int gtid = blockIdx.x * blockDim.x + threadIdx.x;
    int node = gtid >> 4, qlane = gtid & 15;
    if (node >= N_NODES) return;
    int beg = g_off[node];
    int nt  = (g_off[node + 1] - beg) >> 2;
    float4 sum = gather_sum((const float4*)g_y0, beg, nt, qlane);
    float di = g_dinv[node];
    float d2 = di * di;
    float4 o;
    o.x = sum.x * d2; o.y = sum.y * d2; o.z = sum.z * d2; o.w = sum.w * d2;
    ((float4*)g_y1)[(size_t)(node + 1) * 16 + qlane] = o;
}

// y2 = dinv^2 * (A y1)
__global__ void __launch_bounds__(256) k_prop2() {
    int gtid = blockIdx.x * blockDim.x + threadIdx.x;
    int node = gtid >> 4, qlane = gtid & 15;
    if (node >= N_NODES) return;
    int beg = g_off[node];
    int nt  = (g_off[node + 1] - beg) >> 2;
    float4 sum = gather_sum((const float4*)g_y1, beg, nt, qlane);
    float di = g_dinv[node];
    float d2 = di * di;
    float4 o;
    o.x = sum.x * d2; o.y = sum.y * d2; o.z = sum.z * d2; o.w = sum.w * d2;
    ((float4*)g_y2)[(size_t)(node + 1) * 16 + qlane] = o;
}

// out = 0.25*(emb + sdeg*(y1+y2) + dinv*(A y2))
__global__ void __launch_bounds__(256) k_prop_last(const float4* __restrict__ emb,
                                                   float4* __restrict__ out) {
    int gtid = blockIdx.x * blockDim.x + threadIdx.x;
    int node = gtid >> 4, qlane = gtid & 15;
    if (node >= N_NODES) return;
    int beg = g_off[node];
    int nt  = (g_off[node + 1] - beg) >> 2;
    float4 sum = gather_sum((const float4*)g_y2, beg, nt, qlane);

    float di = g_dinv[node];
    float sd = g_sdeg[node];
    size_t yi = (size_t)(node + 1) * 16 + qlane;
    size_t oi = (size_t)node * 16 + qlane;
    float4 e0 = emb[oi];
    float4 a1 = ((const float4*)g_y1)[yi];
    float4 a2 = ((const float4*)g_y2)[yi];
    float4 o;
    o.x = 0.25f * (e0.x + sd * (a1.x + a2.x) + di * sum.x);
    o.y = 0.25f * (e0.y + sd * (a1.y + a2.y) + di * sum.y);
    o.z = 0.25f * (e0.z + sd * (a1.z + a2.z) + di * sum.z);
    o.w = 0.25f * (e0.w + sd * (a1.w + a2.w) + di * sum.w);
    out[oi] = o;
}

// -------------------- launch --------------------

extern "C" void kernel_launch(void* const* d_in, const int* in_sizes, int n_in,
                              void* d_out, int out_size) {
    const int*   edge_index = (const int*)d_in[0];     // int32
    const float* emb_weight = (const float*)d_in[1];
    float*       out        = (float*)d_out;

    void *deg_ptr, *csr_ptr;
    cudaGetSymbolAddress(&deg_ptr, g_deg);
    cudaGetSymbolAddress(&csr_ptr, g_csr);
    cudaMemsetAsync(deg_ptr, 0, N_NODES * sizeof(int), 0);
    cudaMemsetAsync(csr_ptr, 0, CSR_MAX * sizeof(int), 0);

    const int BS = 256;
    int geh = (N_EDGES / 2 + BS - 1) / BS;

    k_degree<<<geh, BS>>>(edge_index);                        // kernel 1 (+part zero)
    k_scan<<<N_SCAN_BLOCKS, SCAN_BS>>>((const float4*)emb_weight); // kernel 2 (+y0,+cur)
    k_scatter<<<geh, BS>>>(edge_index);                       // kernel 3

    int gp = (N_NODES * 16 + BS - 1) / BS;                    // 16 threads per node
    k_prop1<<<gp, BS>>>();                                    // kernel 4 <- ncu (skip 5: 2 memsets + 3 kernels)
    k_prop2<<<gp, BS>>>();                                    // kernel 5
    k_prop_last<<<gp, BS>>>((const float4*)emb_weight, (float4*)out); // kernel 6
}

// round 16
// speedup vs baseline: 1.4684x; 1.2226x over previous
#include <cuda_runtime.h>
#include <cuda_fp16.h>
#include <stdint.h>

#define NUM_USERS 100000
#define NUM_ITEMS 50000
#define N_NODES   (NUM_USERS + NUM_ITEMS)   // 150000
#define EMBED_DIM 64
#define N_EDGES   1000000

#define SCAN_BS   1024
#define N_SCAN_BLOCKS ((N_NODES + SCAN_BS - 1) / SCAN_BS)   // 147

#define A_FLAG (1u << 30)
#define P_FLAG (1u << 31)
#define VAL_MASK 0x3FFFFFFFu

// ---- static device scratch (no allocation allowed) ----
__device__ int      g_deg[N_NODES];
__device__ float    g_dinv[N_NODES];
__device__ int      g_off[N_NODES];        // excl prefix -> end offsets after scatter
__device__ unsigned g_part[N_SCAN_BLOCKS]; // lookback state (zeroed in k_degree)
__device__ int2     g_csr[N_EDGES];        // {src, norm_bits}
// fp16 embeddings: row = 64 halves = 16 lanes x uint2 (8B) = 128 bytes
__device__ uint2    g_h0[N_NODES * 16];
__device__ uint2    g_h1[N_NODES * 16];
__device__ uint2    g_h2[N_NODES * 16];

// -------------------- setup kernels --------------------

// 2 edges per thread (int2 loads); also zeroes lookback state for k_scan.
__global__ void k_degree(const int* __restrict__ edge_index) {
    int t = blockIdx.x * blockDim.x + threadIdx.x;
    if (t < N_SCAN_BLOCKS) g_part[t] = 0;
    if (t < N_EDGES / 2) {
        int2 d2 = ((const int2*)(edge_index + N_EDGES))[t];
        atomicAdd(&g_deg[d2.x], 1);
        atomicAdd(&g_deg[d2.y], 1);
    }
}

// decoupled-lookback exclusive scan of degrees; emits dinv; converts emb->fp16
// for this block's node range in the tail (no separate convert kernel).
__global__ void __launch_bounds__(SCAN_BS) k_scan(const float4* __restrict__ emb) {
    __shared__ int s_wt[32];
    __shared__ int s_run;

    int tid  = threadIdx.x;
    int bid  = blockIdx.x;
    int lane = tid & 31;
    int wid  = tid >> 5;
    int i    = bid * SCAN_BS + tid;

    int v = (i < N_NODES) ? g_deg[i] : 0;
    if (i < N_NODES) g_dinv[i] = (v > 0) ? rsqrtf((float)v) : 0.0f;

    int inc = v;
    #pragma unroll
    for (int d = 1; d < 32; d <<= 1) {
        int t = __shfl_up_sync(0xffffffffu, inc, d);
        if (lane >= d) inc += t;
    }
    if (lane == 31) s_wt[wid] = inc;
    __syncthreads();

    if (wid == 0) {
        int wv = s_wt[lane];
        int winc = wv;
        #pragma unroll
        for (int d = 1; d < 32; d <<= 1) {
            int t = __shfl_up_sync(0xffffffffu, winc, d);
            if (lane >= d) winc += t;
        }
        s_wt[lane] = winc;
        if (lane == 31)
            atomicExch(&g_part[bid], A_FLAG | (unsigned)winc);

        int running = 0;
        int look = bid - 1;
        while (look >= 0) {
            int idx = look - lane;
            unsigned w;
            if (idx >= 0) {
                volatile unsigned* p = (volatile unsigned*)&g_part[idx];
                do { w = *p; } while ((w & (A_FLAG | P_FLAG)) == 0);
            } else {
                w = P_FLAG;
            }
            unsigned pm = __ballot_sync(0xffffffffu, (w & P_FLAG) != 0);
            int firstP = pm ? (__ffs(pm) - 1) : 32;
            int contrib = (lane <= firstP) ? (int)(w & VAL_MASK) : 0;
            #pragma unroll
            for (int d = 16; d; d >>= 1) contrib += __shfl_down_sync(0xffffffffu, contrib, d);
            contrib = __shfl_sync(0xffffffffu, contrib, 0);
            running += contrib;
            if (firstP < 32) break;
            look -= 32;
        }
        if (lane == 31)
            atomicExch(&g_part[bid], P_FLAG | (unsigned)(running + winc));
        if (lane == 0) s_run = running;
    }
    __syncthreads();

    int excl = (wid ? s_wt[wid - 1] : 0) + (inc - v) + s_run;
    if (i < N_NODES) g_off[i] = excl;

    // tail: h0 = fp16(emb) for this block's node range (1:1 float4 -> uint2)
    int base16 = bid * SCAN_BS * 16;
    #pragma unroll
    for (int k = 0; k < 16; k++) {
        int j = base16 + k * SCAN_BS + tid;
        if (j < N_NODES * 16) {
            float4 e = emb[j];
            uint2 o;
            *(__half2*)&o.x = __float22half2_rn(make_float2(e.x, e.y));
            *(__half2*)&o.y = __float22half2_rn(make_float2(e.z, e.w));
            g_h0[j] = o;
        }
    }
}

// scatter 2 edges per thread into CSR-by-dst; single atomic bumps g_off[dst].
__global__ void k_scatter(const int* __restrict__ edge_index) {
    int t = blockIdx.x * blockDim.x + threadIdx.x;
    if (t < N_EDGES / 2) {
        int2 s2 = ((const int2*)edge_index)[t];
        int2 d2 = ((const int2*)(edge_index + N_EDGES))[t];
        int p0 = atomicAdd(&g_off[d2.x], 1);
        g_csr[p0] = make_int2(s2.x, __float_as_int(g_dinv[s2.x] * g_dinv[d2.x]));
        int p1 = atomicAdd(&g_off[d2.y], 1);
        g_csr[p1] = make_int2(s2.y, __float_as_int(g_dinv[s2.y] * g_dinv[d2.y]));
    }
}

// -------------------- propagation --------------------
// 2 nodes per warp: 16 lanes per node, uint2 (4 halves) per lane = 128B row.
// Clamped branchless batches of 4 edges (R9 loop shape), fp32 accumulation.
__device__ __forceinline__ float4 gather_h(const uint2* __restrict__ hx,
                                           int beg, int end, int qlane) {
    float4 sum = make_float4(0.0f, 0.0f, 0.0f, 0.0f);
    int last = end - 1;
    for (int e = beg; e < end; e += 4) {
        int2 p0 = g_csr[e];
        int2 p1 = g_csr[min(e + 1, last)];
        int2 p2 = g_csr[min(e + 2, last)];
        int2 p3 = g_csr[min(e + 3, last)];
        uint2 v0 = hx[(size_t)p0.x * 16 + qlane];
        uint2 v1 = hx[(size_t)p1.x * 16 + qlane];
        uint2 v2 = hx[(size_t)p2.x * 16 + qlane];
        uint2 v3 = hx[(size_t)p3.x * 16 + qlane];
        float w0 = __int_as_float(p0.y);
        float w1 = (e + 1 < end) ? __int_as_float(p1.y) : 0.0f;
        float w2 = (e + 2 < end) ? __int_as_float(p2.y) : 0.0f;
        float w3 = (e + 3 < end) ? __int_as_float(p3.y) : 0.0f;
        float2 f;
        f = __half22float2(*(__half2*)&v0.x); sum.x = fmaf(f.x, w0, sum.x); sum.y = fmaf(f.y, w0, sum.y);
        f = __half22float2(*(__half2*)&v0.y); sum.z = fmaf(f.x, w0, sum.z); sum.w = fmaf(f.y, w0, sum.w);
        f = __half22float2(*(__half2*)&v1.x); sum.x = fmaf(f.x, w1, sum.x); sum.y = fmaf(f.y, w1, sum.y);
        f = __half22float2(*(__half2*)&v1.y); sum.z = fmaf(f.x, w1, sum.z); sum.w = fmaf(f.y, w1, sum.w);
        f = __half22float2(*(__half2*)&v2.x); sum.x = fmaf(f.x, w2, sum.x); sum.y = fmaf(f.y, w2, sum.y);
        f = __half22float2(*(__half2*)&v2.y); sum.z = fmaf(f.x, w2, sum.z); sum.w = fmaf(f.y, w2, sum.w);
        f = __half22float2(*(__half2*)&v3.x); sum.x = fmaf(f.x, w3, sum.x); sum.y = fmaf(f.y, w3, sum.y);
        f = __half22float2(*(__half2*)&v3.y); sum.z = fmaf(f.x, w3, sum.z); sum.w = fmaf(f.y, w3, sum.w);
    }
    return sum;
}

__device__ __forceinline__ uint2 pack_h(float4 s) {
    uint2 o;
    *(__half2*)&o.x = __float22half2_rn(make_float2(s.x, s.y));
    *(__half2*)&o.y = __float22half2_rn(make_float2(s.z, s.w));
    return o;
}

// shifted-offset convention: end = g_off[node], beg = node ? g_off[node-1] : 0
__global__ void __launch_bounds__(256) k_prop1() {
    int gtid = blockIdx.x * blockDim.x + threadIdx.x;
    int node = gtid >> 4, qlane = gtid & 15;
    if (node >= N_NODES) return;
    int end = g_off[node];
    int beg = node ? g_off[node - 1] : 0;
    float4 sum = gather_h(g_h0, beg, end, qlane);
    g_h1[(size_t)node * 16 + qlane] = pack_h(sum);
}

__global__ void __launch_bounds__(256) k_prop2() {
    int gtid = blockIdx.x * blockDim.x + threadIdx.x;
    int node = gtid >> 4, qlane = gtid & 15;
    if (node >= N_NODES) return;
    int end = g_off[node];
    int beg = node ? g_off[node - 1] : 0;
    float4 sum = gather_h(g_h1, beg, end, qlane);
    g_h2[(size_t)node * 16 + qlane] = pack_h(sum);
}

// layer 3 + epilogue: out = 0.25*(emb_fp32 + h1 + h2 + A~*h2)
__global__ void __launch_bounds__(256) k_prop_last(const float4* __restrict__ emb,
                                                   float4* __restrict__ out) {
    int gtid = blockIdx.x * blockDim.x + threadIdx.x;
    int node = gtid >> 4, qlane = gtid & 15;
    if (node >= N_NODES) return;
    int end = g_off[node];
    int beg = node ? g_off[node - 1] : 0;
    float4 sum = gather_h(g_h2, beg, end, qlane);

    size_t oi = (size_t)node * 16 + qlane;
    float4 e0 = emb[oi];
    uint2 u1 = g_h1[oi];
    uint2 u2 = g_h2[oi];
    float2 a1lo = __half22float2(*(__half2*)&u1.x);
    float2 a1hi = __half22float2(*(__half2*)&u1.y);
    float2 a2lo = __half22float2(*(__half2*)&u2.x);
    float2 a2hi = __half22float2(*(__half2*)&u2.y);
    float4 o;
    o.x = 0.25f * (e0.x + a1lo.x + a2lo.x + sum.x);
    o.y = 0.25f * (e0.y + a1lo.y + a2lo.y + sum.y);
    o.z = 0.25f * (e0.z + a1hi.x + a2hi.x + sum.z);
    o.w = 0.25f * (e0.w + a1hi.y + a2hi.y + sum.w);
    out[oi] = o;
}

// -------------------- launch --------------------

extern "C" void kernel_launch(void* const* d_in, const int* in_sizes, int n_in,
                              void* d_out, int out_size) {
    const int*   edge_index = (const int*)d_in[0];     // int32
    const float* emb_weight = (const float*)d_in[1];
    float*       out        = (float*)d_out;

    void* deg_ptr = nullptr;
    cudaGetSymbolAddress(&deg_ptr, g_deg);
    cudaMemsetAsync(deg_ptr, 0, N_NODES * sizeof(int), 0);

    const int BS = 256;
    int geh = (N_EDGES / 2 + BS - 1) / BS;

    k_degree<<<geh, BS>>>(edge_index);                              // kernel 1
    k_scan<<<N_SCAN_BLOCKS, SCAN_BS>>>((const float4*)emb_weight);  // kernel 2 (+h0)
    k_scatter<<<geh, BS>>>(edge_index);                             // kernel 3

    int gp = (N_NODES * 16 + BS - 1) / BS;                          // 16 threads/node
    k_prop1<<<gp, BS>>>();                                          // kernel 4 <- ncu
    k_prop2<<<gp, BS>>>();                                          // kernel 5
    k_prop_last<<<gp, BS>>>((const float4*)emb_weight, (float4*)out); // kernel 6
}